// round 7
// baseline (speedup 1.0000x reference)
#include <cuda_runtime.h>
#include <math.h>
#include <stdint.h>

#define S_LEN 2048
#define B_SZ  64
#define E_SZ  256
#define H_SZ  256

// Scratch for x_proj: [S, B, H] fp32 = 134 MB
__device__ float g_xproj[(size_t)S_LEN * B_SZ * H_SZ];

typedef unsigned long long ull;

// ---- packed f32x2 helpers (Blackwell sm_103a) -------------------------------
__device__ __forceinline__ ull fma2(ull a, ull b, ull c) {
    ull d;
    asm("fma.rn.f32x2 %0, %1, %2, %3;" : "=l"(d) : "l"(a), "l"(b), "l"(c));
    return d;
}
__device__ __forceinline__ ull pack2(float lo, float hi) {
    ull d;
    asm("mov.b64 %0, {%1, %2};" : "=l"(d) : "f"(lo), "f"(hi));
    return d;
}
__device__ __forceinline__ void unpack2(ull v, float& lo, float& hi) {
    asm("mov.b64 {%0, %1}, %2;" : "=f"(lo), "=f"(hi) : "l"(v));
}

// fast tanh: tanh(x) = 1 - 2/(exp(2x)+1), via MUFU.EX2 + MUFU.RCP (~1e-6 err)
__device__ __forceinline__ float fast_tanh(float x) {
    float u, r;
    asm("ex2.approx.f32 %0, %1;" : "=f"(u) : "f"(x * 2.885390082f)); // 2*log2(e)
    asm("rcp.approx.f32 %0, %1;" : "=f"(r) : "f"(u + 1.0f));
    return fmaf(-2.0f, r, 1.0f);
}

__device__ __forceinline__ uint32_t smem_u32(const void* p) {
    uint32_t a;
    asm("{ .reg .u64 t; cvta.to.shared.u64 t, %1; cvt.u32.u64 %0, t; }"
        : "=r"(a) : "l"(p));
    return a;
}
__device__ __forceinline__ void cp_async16(uint32_t saddr, const void* gaddr) {
    asm volatile("cp.async.cg.shared.global [%0], [%1], 16;"
                 :: "r"(saddr), "l"(gaddr) : "memory");
}

// ---------------------------------------------------------------------------
// Kernel 1: x_proj = sentence @ W_ih + b  (R4 version — measured ~393us)
// ---------------------------------------------------------------------------
__global__ __launch_bounds__(256) void xproj_kernel(
    const float* __restrict__ sent,
    const float* __restrict__ Wih,
    const float* __restrict__ bias)
{
    __shared__ float xs[8][256];
    __shared__ float part[4][8][256];

    const int t  = threadIdx.x;
    const int m0 = blockIdx.x * 8;

    {
        const float4* srow = (const float4*)(sent + (size_t)m0 * 256);
        float4* xs4 = (float4*)&xs[0][0];
        #pragma unroll
        for (int i = 0; i < 2; i++)
            xs4[t + i * 256] = srow[t + i * 256];
    }
    __syncthreads();

    const int jg = t & 63;
    const int ks = t >> 6;
    const float4* W4 = (const float4*)Wih;

    float4 acc[8];
    #pragma unroll
    for (int r = 0; r < 8; r++) acc[r] = make_float4(0.f, 0.f, 0.f, 0.f);

    #pragma unroll 8
    for (int i = 0; i < 64; i++) {
        const int k = ks * 64 + i;
        const float4 w = W4[k * 64 + jg];
        #pragma unroll
        for (int r = 0; r < 8; r++) {
            const float xv = xs[r][k];
            acc[r].x += xv * w.x;
            acc[r].y += xv * w.y;
            acc[r].z += xv * w.z;
            acc[r].w += xv * w.w;
        }
    }

    #pragma unroll
    for (int r = 0; r < 8; r++)
        *(float4*)&part[ks][r][4 * jg] = acc[r];
    __syncthreads();

    const float bj = bias[t];
    #pragma unroll
    for (int r = 0; r < 8; r++) {
        const float v = part[0][r][t] + part[1][r][t] +
                        part[2][r][t] + part[3][r][t] + bj;
        g_xproj[(size_t)(m0 + r) * 256 + t] = v;
    }
}

// ---------------------------------------------------------------------------
// Kernel 2: the scan. 64 CTAs (1 batch row each), 256 threads.
// ks = t>>5 (8-way k-split, 32 k's), jq = t&31 (8 cols).
// W: 24 k's in registers (192 regs), 8 k's in SMEM (64 KB).
// NEW vs R6 (latency attack):
//  - x_proj block-prefetched 8 steps ahead via cp.async double-buffer ring
//  - fast_tanh (2 MUFU) instead of tanhf slow path
//  - reduce phase uses ALL 256 threads on scalar partials
// ---------------------------------------------------------------------------
#define K_REG  24
#define K_SMEM 8
#define XBLK   8

__global__ __launch_bounds__(256, 1) void scan_kernel(
    const float* __restrict__ Whh,    // [256,256] row-major (k, j)
    const float* __restrict__ h0,     // [64,256]
    float* __restrict__ out)          // [64,256]
{
    extern __shared__ ull smem[];
    ulonglong2* sW     = (ulonglong2*)smem;            // 4096 entries, 64 KB
    ull*        part   = (ull*)(sW + 4096);            // 1024 ull, 8 KB
    ull*        hbuf   = part + 1024;                  // 256 ull, 2 KB
    float*      xs     = (float*)(hbuf + 256);         // [2][8][256], 16 KB
    float*      part_f = (float*)part;                 // scalar view [8][256]

    const int t  = threadIdx.x;
    const int b  = blockIdx.x;
    const int ks = t >> 5;          // 0..7
    const int jq = t & 31;          // owns cols 8jq .. 8jq+7
    const int kbase = ks * 32;

    // ---- one-time: register-resident W (24 k's x 8 cols) ----
    ull wr[4 * K_REG];
    #pragma unroll
    for (int i = 0; i < K_REG; i++) {
        const float* wrow = &Whh[(size_t)(kbase + i) * 256 + 8 * jq];
        const ulonglong2 wa = *(const ulonglong2*)(wrow);
        const ulonglong2 wb = *(const ulonglong2*)(wrow + 4);
        wr[4 * i + 0] = wa.x;
        wr[4 * i + 1] = wa.y;
        wr[4 * i + 2] = wb.x;
        wr[4 * i + 3] = wb.y;
    }

    // ---- one-time: SMEM W (8 k's per ks-group) ----
    for (int idx = t; idx < 8 * K_SMEM * 32 * 2; idx += 256) {
        const int half = idx & 1;
        const int fjq  = (idx >> 1) & 31;
        const int fm   = (idx >> 6) % K_SMEM;
        const int fks  = idx / (K_SMEM * 32 * 2);
        const int k    = fks * 32 + K_REG + fm;
        sW[idx] = *(const ulonglong2*)&Whh[(size_t)k * 256 + 8 * fjq + 4 * half];
    }

    // ---- init h (replicated pairs) ----
    {
        const float ha = h0[(size_t)b * 256 + t];
        hbuf[t] = pack2(ha, ha);
    }

    // ---- prologue: prefetch x block 0 into buf 0 ----
    const uint32_t xs_base = smem_u32(xs);
    {
        #pragma unroll
        for (int i = t; i < 512; i += 256) {       // 512 float4 per block
            const int r  = i >> 6;
            const int c4 = (i & 63) * 4;
            cp_async16(xs_base + (uint32_t)((0 * XBLK + r) * 256 + c4) * 4,
                       &g_xproj[((size_t)r * B_SZ + b) * 256 + c4]);
        }
        asm volatile("cp.async.commit_group;" ::: "memory");
    }
    __syncthreads();

    const ull* hb = hbuf + kbase;
    const ulonglong2* sWg = sW + (size_t)(ks * K_SMEM) * 64 + jq * 2;
    const int NBLK = S_LEN / XBLK;   // 256

    for (int blk = 0; blk < NBLK; blk++) {
        const int buf = blk & 1;

        // prefetch next block into the other buffer, then wait for this one
        if (blk + 1 < NBLK) {
            #pragma unroll
            for (int i = t; i < 512; i += 256) {
                const int r  = i >> 6;
                const int c4 = (i & 63) * 4;
                cp_async16(
                    xs_base + (uint32_t)(((buf ^ 1) * XBLK + r) * 256 + c4) * 4,
                    &g_xproj[((size_t)((blk + 1) * XBLK + r) * B_SZ + b) * 256 + c4]);
            }
            asm volatile("cp.async.commit_group;" ::: "memory");
            asm volatile("cp.async.wait_group 1;" ::: "memory");
        } else {
            asm volatile("cp.async.wait_group 0;" ::: "memory");
        }
        // visibility of this block's xs to all threads: BAR (A) inside step 0
        // of this block precedes the first consumption (reduce phase).

        #pragma unroll 2
        for (int si = 0; si < XBLK; si++) {
            ull a0 = 0, a1 = 0, a2 = 0, a3 = 0;

            // register half: k = kbase + 0 .. kbase + 23
            #pragma unroll
            for (int p = 0; p < K_REG / 2; p++) {
                const ulonglong2 hv = *(const ulonglong2*)(hb + 2 * p);
                a0 = fma2(wr[8 * p + 0], hv.x, a0);
                a1 = fma2(wr[8 * p + 1], hv.x, a1);
                a2 = fma2(wr[8 * p + 2], hv.x, a2);
                a3 = fma2(wr[8 * p + 3], hv.x, a3);
                a0 = fma2(wr[8 * p + 4], hv.y, a0);
                a1 = fma2(wr[8 * p + 5], hv.y, a1);
                a2 = fma2(wr[8 * p + 6], hv.y, a2);
                a3 = fma2(wr[8 * p + 7], hv.y, a3);
            }
            // smem half: k = kbase + 24 .. kbase + 31
            #pragma unroll
            for (int m = 0; m < K_SMEM; m++) {
                const ull hv = hb[K_REG + m];
                const ulonglong2 w0 = sWg[m * 64];
                const ulonglong2 w1 = sWg[m * 64 + 1];
                a0 = fma2(w0.x, hv, a0);
                a1 = fma2(w0.y, hv, a1);
                a2 = fma2(w1.x, hv, a2);
                a3 = fma2(w1.y, hv, a3);
            }

            part[ks * 128 + 4 * jq + 0] = a0;
            part[ks * 128 + 4 * jq + 1] = a1;
            part[ks * 128 + 4 * jq + 2] = a2;
            part[ks * 128 + 4 * jq + 3] = a3;
            __syncthreads();     // (A) partials visible; hbuf reads done

            // reduce: ALL 256 threads, thread t owns column t (scalar)
            {
                const float v0 = part_f[0 * 256 + t] + part_f[1 * 256 + t];
                const float v1 = part_f[2 * 256 + t] + part_f[3 * 256 + t];
                const float v2 = part_f[4 * 256 + t] + part_f[5 * 256 + t];
                const float v3 = part_f[6 * 256 + t] + part_f[7 * 256 + t];
                const float xv = xs[(buf * XBLK + si) * 256 + t];
                const float v  = ((v0 + v1) + (v2 + v3)) + xv;
                const float h  = fast_tanh(v);
                hbuf[t] = pack2(h, h);
            }
            __syncthreads();     // (B) new h visible
        }
    }

    // final h (replicated pairs) -> out
    {
        float vx, vy;
        unpack2(hbuf[t], vx, vy);
        out[(size_t)b * 256 + t] = vx;
    }
}

// ---------------------------------------------------------------------------
extern "C" void kernel_launch(void* const* d_in, const int* in_sizes, int n_in,
                              void* d_out, int out_size)
{
    const float* sentence = (const float*)d_in[0];
    const float* h0       = (const float*)d_in[1];
    const float* W_ih     = (const float*)d_in[2];
    const float* W_hh     = (const float*)d_in[3];
    const float* bias     = (const float*)d_in[4];
    float* out = (float*)d_out;

    (void)in_sizes; (void)n_in; (void)out_size;

    xproj_kernel<<<(S_LEN * B_SZ) / 8, 256>>>(sentence, W_ih, bias);

    // smem: sW 64KB + part 8KB + hbuf 2KB + xs 16KB = 90KB
    const int smem_bytes = 4096 * 16 + 1024 * 8 + 256 * 8 + 2 * XBLK * 256 * 4;
    cudaFuncSetAttribute(scan_kernel,
                         cudaFuncAttributeMaxDynamicSharedMemorySize,
                         smem_bytes);
    scan_kernel<<<B_SZ, 256, smem_bytes>>>(W_hh, h0, out);
}